// round 3
// baseline (speedup 1.0000x reference)
#include <cuda_runtime.h>
#include <cstdint>
#include <cstddef>

#define NB_ROWS 2048
#define NCOMBO  64
#define NSTRUCT 512
#define NHID    1024
#define NITER   60
#define MAXNNZ  (NCOMBO * NSTRUCT)
#define SMNNZ   4096
#define XBSTR   10   // padded batch stride (floats) for s_xbar: bank class = col mod 16
#define YHSTR   10   // padded batch stride for s_yhead

// ---------------- device scratch (static, allocation-free) ----------------
__device__ float g_C1[NB_ROWS * NHID];
__device__ float g_C2[NB_ROWS * NHID];
__device__ float g_Z [NB_ROWS * NSTRUCT];
__device__ int            g_row_ptr[NCOMBO + 1];
__device__ unsigned short g_csr_cols[MAXNNZ];
__device__ int            g_col_ptr[NSTRUCT + 1];
__device__ unsigned short g_csc_rows[MAXNNZ];
__device__ float g_tau;

// ---------------- cp.async helpers ---------------------------------------
__device__ __forceinline__ void cp_async16(void* smem, const void* gmem) {
    unsigned s = (unsigned)__cvta_generic_to_shared(smem);
    asm volatile("cp.async.cg.shared.global [%0], [%1], 16;\n" :: "r"(s), "l"(gmem));
}
__device__ __forceinline__ void cp_commit() {
    asm volatile("cp.async.commit_group;\n");
}
template<int N_> __device__ __forceinline__ void cp_wait() {
    asm volatile("cp.async.wait_group %0;\n" :: "n"(N_));
}

// ---------------- prep: build CSR/CSC of S + power iteration -> g_tau ----
__global__ void prep_kernel(const float* __restrict__ S)
{
    __shared__ unsigned char s8[NCOMBO * NSTRUCT];   // 32KB: S as 0/1 bytes
    __shared__ float v[NSTRUCT];
    __shared__ float sv[NCOMBO];
    __shared__ float red[16];
    __shared__ int   scnt[NCOMBO];
    __shared__ int   wtot[16];

    const int t    = threadIdx.x;        // 512 threads
    const int lane = t & 31;
    const int wid  = t >> 5;

    #pragma unroll 4
    for (int i = 0; i < NCOMBO; i++)
        s8[i * NSTRUCT + t] = (S[i * NSTRUCT + t] != 0.0f) ? 1 : 0;
    __syncthreads();

    // ---- CSR (row lists) ----
    if (t < NCOMBO) {
        int c = 0;
        for (int j = 0; j < NSTRUCT; j++) c += s8[t * NSTRUCT + j];
        scnt[t] = c;
    }
    __syncthreads();
    if (t == 0) {
        int acc = 0;
        for (int i = 0; i < NCOMBO; i++) { g_row_ptr[i] = acc; acc += scnt[i]; }
        g_row_ptr[NCOMBO] = acc;
    }
    __syncthreads();
    if (t < NCOMBO) {
        int p = g_row_ptr[t];
        for (int j = 0; j < NSTRUCT; j++)
            if (s8[t * NSTRUCT + j]) g_csr_cols[p++] = (unsigned short)j;
    }

    // ---- CSC (column lists) via block scan over 512 counts ----
    int cc = 0;
    for (int i = 0; i < NCOMBO; i++) cc += s8[i * NSTRUCT + t];
    int incl = cc;
    #pragma unroll
    for (int o = 1; o < 32; o <<= 1) {
        int nbr = __shfl_up_sync(0xffffffffu, incl, o);
        if (lane >= o) incl += nbr;
    }
    if (lane == 31) wtot[wid] = incl;
    __syncthreads();
    if (t < 16) {
        int xv = wtot[t];
        #pragma unroll
        for (int o = 1; o < 16; o <<= 1) {
            int nbr = __shfl_up_sync(0x0000ffffu, xv, o);
            if (t >= o) xv += nbr;
        }
        wtot[t] = xv;
    }
    __syncthreads();
    {
        int base = (wid > 0) ? wtot[wid - 1] : 0;
        int cend = base + incl;              // inclusive -> col_ptr[t+1]
        g_col_ptr[t + 1] = cend;
        if (t == 0) g_col_ptr[0] = 0;
        int p = cend - cc;
        for (int i = 0; i < NCOMBO; i++)
            if (s8[i * NSTRUCT + t]) g_csc_rows[p++] = (unsigned short)i;
    }
    __syncthreads();

    // ---- power iteration on S^T S + I ----
    v[t] = 1.0f / sqrtf((float)NSTRUCT);
    __syncthreads();
    for (int step = 0; step < 30; step++) {
        if (t < NCOMBO) {
            float a = 0.f;
            const int e = g_row_ptr[t + 1];
            for (int p = g_row_ptr[t]; p < e; p++) a += v[g_csr_cols[p]];
            sv[t] = a;
        }
        __syncthreads();
        float w = v[t];
        {
            const int e = g_col_ptr[t + 1];
            for (int p = g_col_ptr[t]; p < e; p++) w += sv[g_csc_rows[p]];
        }
        float sq = w * w;
        #pragma unroll
        for (int o = 16; o > 0; o >>= 1) sq += __shfl_xor_sync(0xffffffffu, sq, o);
        if (lane == 0) red[wid] = sq;
        __syncthreads();
        if (t == 0) {
            float s = 0.f;
            #pragma unroll
            for (int i = 0; i < 16; i++) s += red[i];
            red[0] = sqrtf(s);
        }
        __syncthreads();
        v[t] = w / red[0];
        __syncthreads();
    }
    // L = sqrt(v . (S^T S v + v));  tau = sigma = 0.9/L
    if (t < NCOMBO) {
        float a = 0.f;
        const int e = g_row_ptr[t + 1];
        for (int p = g_row_ptr[t]; p < e; p++) a += v[g_csr_cols[p]];
        sv[t] = a;
    }
    __syncthreads();
    {
        float w = v[t];
        const int e = g_col_ptr[t + 1];
        for (int p = g_col_ptr[t]; p < e; p++) w += sv[g_csc_rows[p]];
        float sq = v[t] * w;
        #pragma unroll
        for (int o = 16; o > 0; o >>= 1) sq += __shfl_xor_sync(0xffffffffu, sq, o);
        if (lane == 0) red[wid] = sq;
        __syncthreads();
        if (t == 0) {
            float s = 0.f;
            #pragma unroll
            for (int i = 0; i < 16; i++) s += red[i];
            g_tau = 0.9f / sqrtf(s);
        }
    }
}

// ---------------- fp32 GEMM + bias + relu, cp.async double-buffered ------
template<int BM, int BN, int THREADS, int K, int N>
__device__ __forceinline__ void sgemm_v2(
    const float* __restrict__ A, const float* __restrict__ B,
    const float* __restrict__ bias, float* __restrict__ C)
{
    constexpr int KC = 16;
    constexpr int CA = BM * KC / 4;
    constexpr int CB = KC * BN / 4;
    constexpr int NSTAGE = K / KC;
    __shared__ float As[2][BM][KC];
    __shared__ float Bs[2][KC][BN];

    const int tid = threadIdx.x;
    const int m0  = blockIdx.y * BM;
    const int n0  = blockIdx.x * BN;
    constexpr int TX = BN / 8;
    const int tx = tid % TX;
    const int ty = tid / TX;
    const int rowA = ty * 4;
    const int colA = tx * 4;

    float acc[8][8];
    #pragma unroll
    for (int i = 0; i < 8; i++)
        #pragma unroll
        for (int j = 0; j < 8; j++) acc[i][j] = 0.f;

    // prologue: stage 0
    {
        #pragma unroll
        for (int c = tid; c < CA; c += THREADS) {
            int m  = c >> 2;
            int kq = (c & 3) * 4;
            cp_async16(&As[0][m][kq], A + (size_t)(m0 + m) * K + kq);
        }
        #pragma unroll
        for (int c = tid; c < CB; c += THREADS) {
            int kr = c / (BN / 4);
            int nq = (c % (BN / 4)) * 4;
            cp_async16(&Bs[0][kr][nq], B + (size_t)kr * N + n0 + nq);
        }
        cp_commit();
    }

    for (int s = 0; s < NSTAGE; s++) {
        if (s + 1 < NSTAGE) {
            const int k0 = (s + 1) * KC;
            const int nb = (s + 1) & 1;
            #pragma unroll
            for (int c = tid; c < CA; c += THREADS) {
                int m  = c >> 2;
                int kq = (c & 3) * 4;
                cp_async16(&As[nb][m][kq], A + (size_t)(m0 + m) * K + k0 + kq);
            }
            #pragma unroll
            for (int c = tid; c < CB; c += THREADS) {
                int kr = c / (BN / 4);
                int nq = (c % (BN / 4)) * 4;
                cp_async16(&Bs[nb][kr][nq], B + (size_t)(k0 + kr) * N + n0 + nq);
            }
            cp_commit();
            cp_wait<1>();
        } else {
            cp_wait<0>();
        }
        __syncthreads();
        const int buf = s & 1;
        #pragma unroll
        for (int kk = 0; kk < KC; kk++) {
            float fa[8], fb[8];
            #pragma unroll
            for (int i = 0; i < 4; i++) {
                fa[i]     = As[buf][rowA + i][kk];
                fa[4 + i] = As[buf][rowA + BM / 2 + i][kk];
            }
            *(float4*)&fb[0] = *(const float4*)&Bs[buf][kk][colA];
            *(float4*)&fb[4] = *(const float4*)&Bs[buf][kk][colA + BN / 2];
            #pragma unroll
            for (int i = 0; i < 8; i++)
                #pragma unroll
                for (int j = 0; j < 8; j++)
                    acc[i][j] = fmaf(fa[i], fb[j], acc[i][j]);
        }
        __syncthreads();
    }

    // epilogue: bias + relu, float4 stores
    float4 bl = *(const float4*)(bias + n0 + colA);
    float4 bh = *(const float4*)(bias + n0 + colA + BN / 2);
    #pragma unroll
    for (int half = 0; half < 2; half++) {
        #pragma unroll
        for (int i = 0; i < 4; i++) {
            const int m  = m0 + rowA + half * (BM / 2) + i;
            const int ai = half * 4 + i;
            float4 o;
            o.x = fmaxf(acc[ai][0] + bl.x, 0.f);
            o.y = fmaxf(acc[ai][1] + bl.y, 0.f);
            o.z = fmaxf(acc[ai][2] + bl.z, 0.f);
            o.w = fmaxf(acc[ai][3] + bl.w, 0.f);
            *(float4*)(C + (size_t)m * N + n0 + colA) = o;
            float4 p;
            p.x = fmaxf(acc[ai][4] + bh.x, 0.f);
            p.y = fmaxf(acc[ai][5] + bh.y, 0.f);
            p.z = fmaxf(acc[ai][6] + bh.z, 0.f);
            p.w = fmaxf(acc[ai][7] + bh.w, 0.f);
            *(float4*)(C + (size_t)m * N + n0 + colA + BN / 2) = p;
        }
    }
}

__global__ __launch_bounds__(256, 2) void gemm1_kernel(
    const float* __restrict__ X, const float* __restrict__ W1, const float* __restrict__ b1)
{ sgemm_v2<128, 128, 256, NCOMBO, NHID>(X, W1, b1, g_C1); }

__global__ __launch_bounds__(256, 2) void gemm2_kernel(
    const float* __restrict__ W2, const float* __restrict__ b2)
{ sgemm_v2<128, 128, 256, NHID, NHID>(g_C1, W2, b2, g_C2); }

__global__ __launch_bounds__(128, 2) void gemm3_kernel(
    const float* __restrict__ W3, const float* __restrict__ b3)
{ sgemm_v2<64, 128, 128, NHID, NSTRUCT>(g_C2, W3, b3, g_Z); }

// ---------------- PDHG v3: padded strides + unrolled gathers --------------
// thread = (dl 0..63, b2 0..3). Each thread owns 2 batch rows (float2) and
// 8 x-columns (j = k*64+dl), plus head row i = dl. 3 barriers / iteration.
__global__ __launch_bounds__(256, 2) void pdhg_kernel(
    const float* __restrict__ Xg, float* __restrict__ out)
{
    __shared__ float s_xbar[NSTRUCT * XBSTR];    // 20KB  [j][batch8 pad10]
    __shared__ float s_yhead[NCOMBO * YHSTR];    // 2.5KB [i][batch8 pad10]
    __shared__ unsigned short s_csr[SMNNZ];      // 8KB
    __shared__ unsigned short s_csc[SMNNZ];      // 8KB
    __shared__ int    s_rp[NCOMBO + 1];
    __shared__ int    s_cp[NSTRUCT + 1];
    __shared__ float2 s_red[8][5];

    const int tid = threadIdx.x;
    const int b2  = tid & 3;        // batch pair 0..3
    const int dl  = tid >> 2;       // dim lane 0..63
    const int wid = tid >> 5;
    const int r0  = blockIdx.x * 8 + b2 * 2;
    const int bo  = b2 * 2;         // float offset within padded batch group

    for (int p = tid; p < NCOMBO + 1;  p += 256) s_rp[p] = g_row_ptr[p];
    for (int p = tid; p < NSTRUCT + 1; p += 256) s_cp[p] = g_col_ptr[p];
    __syncthreads();
    const int nnz = s_rp[NCOMBO];
    for (int p = tid; p < nnz && p < SMNNZ; p += 256) {
        s_csr[p] = g_csr_cols[p];
        s_csc[p] = g_csc_rows[p];
    }
    const unsigned short* __restrict__ csr = (nnz <= SMNNZ) ? s_csr : g_csr_cols;
    const unsigned short* __restrict__ csc = (nnz <= SMNNZ) ? s_csc : g_csc_rows;
    const float tau = g_tau;

    float2 x[8], z[8], yt[8], xb[8];
    #pragma unroll
    for (int k = 0; k < 8; k++) {
        const int j = k * 64 + dl;
        z[k].x = g_Z[(size_t)r0 * NSTRUCT + j];
        z[k].y = g_Z[(size_t)(r0 + 1) * NSTRUCT + j];
        x[k]  = make_float2(0.f, 0.f);
        yt[k] = make_float2(0.f, 0.f);
        xb[k] = make_float2(0.f, 0.f);
        *(float2*)&s_xbar[j * XBSTR + bo] = make_float2(0.f, 0.f);
    }
    const int i = dl;
    float2 Bv = make_float2(Xg[(size_t)r0 * NCOMBO + i],
                            Xg[(size_t)(r0 + 1) * NCOMBO + i]);
    float2 yh = make_float2(0.f, 0.f);
    const int rs = s_rp[i], re = s_rp[i + 1];
    __syncthreads();

    for (int it = 0; it < NITER; it++) {
        // ---- phase A: y-head (Kx over CSR, unroll x4) + y-tail ----
        {
            float a0x = 0.f, a0y = 0.f, a1x = 0.f, a1y = 0.f;
            float a2x = 0.f, a2y = 0.f, a3x = 0.f, a3y = 0.f;
            int p = rs;
            for (; p + 3 < re; p += 4) {
                const int c0 = csr[p], c1 = csr[p + 1];
                const int c2 = csr[p + 2], c3 = csr[p + 3];
                float2 v0 = *(const float2*)&s_xbar[c0 * XBSTR + bo];
                float2 v1 = *(const float2*)&s_xbar[c1 * XBSTR + bo];
                float2 v2 = *(const float2*)&s_xbar[c2 * XBSTR + bo];
                float2 v3 = *(const float2*)&s_xbar[c3 * XBSTR + bo];
                a0x += v0.x; a0y += v0.y;
                a1x += v1.x; a1y += v1.y;
                a2x += v2.x; a2y += v2.y;
                a3x += v3.x; a3y += v3.y;
            }
            for (; p < re; p++) {
                float2 v = *(const float2*)&s_xbar[csr[p] * XBSTR + bo];
                a0x += v.x; a0y += v.y;
            }
            const float ax = (a0x + a1x) + (a2x + a3x);
            const float ay = (a0y + a1y) + (a2y + a3y);
            yh.x = fmaxf(yh.x + tau * (ax - Bv.x), 0.f);
            yh.y = fmaxf(yh.y + tau * (ay - Bv.y), 0.f);
            *(float2*)&s_yhead[i * YHSTR + bo] = yh;
        }
        #pragma unroll
        for (int k = 0; k < 8; k++) {
            yt[k].x = fmaxf(yt[k].x - tau * xb[k].x, 0.f);
            yt[k].y = fmaxf(yt[k].y - tau * xb[k].y, 0.f);
        }
        __syncthreads();

        // ---- phase B: KTy over CSC (unroll x2) + prox residual ----
        float2 d[8];
        float ssx = 0.f, ssy = 0.f;
        #pragma unroll
        for (int k = 0; k < 8; k++) {
            const int j = k * 64 + dl;
            float t0x = -yt[k].x, t0y = -yt[k].y;
            float t1x = 0.f, t1y = 0.f;
            const int cs = s_cp[j], ce = s_cp[j + 1];
            int p = cs;
            for (; p + 1 < ce; p += 2) {
                const int ra = csc[p], rb = csc[p + 1];
                float2 va = *(const float2*)&s_yhead[ra * YHSTR + bo];
                float2 vb = *(const float2*)&s_yhead[rb * YHSTR + bo];
                t0x += va.x; t0y += va.y;
                t1x += vb.x; t1y += vb.y;
            }
            if (p < ce) {
                float2 v = *(const float2*)&s_yhead[csc[p] * YHSTR + bo];
                t0x += v.x; t0y += v.y;
            }
            const float tvx = t0x + t1x;
            const float tvy = t0y + t1y;
            const float dx = x[k].x - tau * tvx + tau - z[k].x;
            const float dy = x[k].y - tau * tvy + tau - z[k].y;
            d[k] = make_float2(dx, dy);
            ssx += dx * dx;
            ssy += dy * dy;
        }
        // reduce over dl within warp (lanes differing in dl bits only)
        ssx += __shfl_xor_sync(0xffffffffu, ssx, 4);
        ssy += __shfl_xor_sync(0xffffffffu, ssy, 4);
        ssx += __shfl_xor_sync(0xffffffffu, ssx, 8);
        ssy += __shfl_xor_sync(0xffffffffu, ssy, 8);
        ssx += __shfl_xor_sync(0xffffffffu, ssx, 16);
        ssy += __shfl_xor_sync(0xffffffffu, ssy, 16);
        if ((tid & 31) < 4) s_red[wid][b2] = make_float2(ssx, ssy);
        __syncthreads();

        // ---- phase C: scale + x/xbar update ----
        float totx = 0.f, toty = 0.f;
        #pragma unroll
        for (int w = 0; w < 8; w++) {
            float2 r = s_red[w][b2];
            totx += r.x; toty += r.y;
        }
        const float scx = fmaxf(1.f - tau / fmaxf(sqrtf(totx), 1e-12f), 0.f);
        const float scy = fmaxf(1.f - tau / fmaxf(sqrtf(toty), 1e-12f), 0.f);
        #pragma unroll
        for (int k = 0; k < 8; k++) {
            const float xnx = z[k].x + scx * d[k].x;
            const float xny = z[k].y + scy * d[k].y;
            float2 xbn = make_float2(2.f * xnx - x[k].x, 2.f * xny - x[k].y);
            x[k]  = make_float2(xnx, xny);
            xb[k] = xbn;
            *(float2*)&s_xbar[(k * 64 + dl) * XBSTR + bo] = xbn;
        }
        __syncthreads();
    }

    #pragma unroll
    for (int k = 0; k < 8; k++) {
        const int j = k * 64 + dl;
        out[(size_t)r0 * NSTRUCT + j]       = x[k].x;
        out[(size_t)(r0 + 1) * NSTRUCT + j] = x[k].y;
    }
}

// ---------------- launch -------------------------------------------------
extern "C" void kernel_launch(void* const* d_in, const int* in_sizes, int n_in,
                              void* d_out, int out_size)
{
    const float* X  = (const float*)d_in[0];
    const float* W1 = (const float*)d_in[1];
    const float* b1 = (const float*)d_in[2];
    const float* W2 = (const float*)d_in[3];
    const float* b2 = (const float*)d_in[4];
    const float* W3 = (const float*)d_in[5];
    const float* b3 = (const float*)d_in[6];
    const float* S  = (const float*)d_in[7];
    float* out = (float*)d_out;

    prep_kernel<<<1, 512>>>(S);

    gemm1_kernel<<<dim3(NHID / 128,    NB_ROWS / 128), 256>>>(X, W1, b1);
    gemm2_kernel<<<dim3(NHID / 128,    NB_ROWS / 128), 256>>>(W2, b2);
    gemm3_kernel<<<dim3(NSTRUCT / 128, NB_ROWS / 64),  128>>>(W3, b3);

    pdhg_kernel<<<NB_ROWS / 8, 256>>>(X, out);
}